// round 8
// baseline (speedup 1.0000x reference)
#include <cuda_runtime.h>

// LocalizeAttention gather: out[bh, n, f, :] = x[bh, n + shift_f, :] (zero at edges).
// BH=16, H=W=D=24 (N=13824), d=32 floats, 27 filters.
// R8: persistent-CTA version of the R6 tiled kernel. 456 resident blocks
// (152 SMs x 3) loop over all 3072 tiles -> no wave-transition drains, no
// wave-quantization tail (last-block skew ~ one tile time).

#define HH 24
#define WW 24
#define DD 24
#define NN (HH * WW * DD)      // 13824
#define FN 27
#define ROW4 8                 // float4 per feature row (32 floats)
#define JT 3                   // j-rows per tile
#define LJ (JT + 2)            // 5 (with halo)
#define LK (DD + 2)            // 26 (with halo)
#define LROWS (3 * LJ * LK)    // 390 source rows in tile
#define THREADS 576            // = JT*DD*8 write lanes
#define JTILES (WW / JT)       // 8
#define PERSIST_BLOCKS 456     // 152 SMs * 3 resident CTAs

__global__ void __launch_bounds__(THREADS, 3)
localize_kernel(const float4* __restrict__ x, float4* __restrict__ out, int ntiles)
{
    __shared__ float4 s[LROWS * ROW4];   // 3120 float4 = 49920 B

    const int t    = threadIdx.x;
    const int d4   = t & 7;
    const int nl   = t >> 3;          // 0..71
    const int jl   = nl / DD;         // 0..2
    const int kq   = nl - jl * DD;    // 0..23
    const float4 zero = make_float4(0.f, 0.f, 0.f, 0.f);

    for (int tile = blockIdx.x; tile < ntiles; tile += PERSIST_BLOCKS) {
        // tile = (bh * HH + i) * JTILES + jt
        int jt  = tile & 7;                 // JTILES = 8
        int bi  = tile >> 3;
        int i   = bi % HH;
        int bh  = bi / HH;
        int j0  = jt * JT;

        // ---- Load phase: tile + halo, zeros outside the volume ----
        for (int l4 = t; l4 < LROWS * ROW4; l4 += THREADS) {
            int dd4 = l4 & 7;
            int row = l4 >> 3;
            int li  = row / (LJ * LK);
            int r   = row - li * (LJ * LK);
            int lj  = r / LK;
            int lk  = r - lj * LK;
            int ii  = i  + li - 1;
            int jj  = j0 + lj - 1;
            int kk  = lk - 1;
            float4 v = zero;
            if ((unsigned)ii < HH && (unsigned)jj < WW && (unsigned)kk < DD) {
                v = __ldg(&x[((size_t)bh * NN + ii * (WW * DD) + jj * DD + kk) * ROW4 + dd4]);
            }
            s[l4] = v;
        }
        __syncthreads();

        // ---- Write phase: one thread per (jl, k, d4); 27 SMEM reads + stores ----
        const int n = i * (WW * DD) + (j0 + jl) * DD + kq;
        float4* dst = out + ((size_t)bh * NN + n) * (FN * ROW4) + d4;
        const float4* sp = s + ((size_t)jl * LK + kq) * ROW4 + d4;

        #pragma unroll
        for (int fi = 0; fi < 3; fi++) {
            #pragma unroll
            for (int fj = 0; fj < 3; fj++) {
                #pragma unroll
                for (int fk = 0; fk < 3; fk++) {
                    const int soff = ((fi * LJ + fj) * LK + fk) * ROW4;
                    __stcs(dst + ((fi * 3 + fj) * 3 + fk) * ROW4, sp[soff]);
                }
            }
        }
        __syncthreads();   // protect smem before next tile's load phase
    }
}

extern "C" void kernel_launch(void* const* d_in, const int* in_sizes, int n_in,
                              void* d_out, int out_size)
{
    const float4* x = (const float4*)d_in[0];
    float4* out = (float4*)d_out;

    int BH = out_size / (NN * FN * 32);     // batch*heads (16 for reference shapes)
    int ntiles = BH * HH * JTILES;          // 3072
    localize_kernel<<<PERSIST_BLOCKS, THREADS>>>(x, out, ntiles);
}

// round 9
// speedup vs baseline: 1.0580x; 1.0580x over previous
#include <cuda_runtime.h>

// LocalizeAttention gather: out[bh, n, f, :] = x[bh, n + shift_f, :] (zero at edges).
// BH=16, H=W=D=24 (N=13824), d=32 floats, 27 filters.
// R9: identical to R6 (best, 119.3us) except stores use DEFAULT cache policy
// instead of __stcs. Theory: evict-first dirty lines force early, poorly
// batched L2->DRAM writebacks; default policy lets the DRAM scheduler batch
// longer row hits on the 732 MB write stream.

#define HH 24
#define WW 24
#define DD 24
#define NN (HH * WW * DD)      // 13824
#define FN 27
#define ROW4 8                 // float4 per feature row (32 floats)
#define JT 3                   // j-rows per block
#define LJ (JT + 2)            // 5 (with halo)
#define LK (DD + 2)            // 26 (with halo)
#define LROWS (3 * LJ * LK)    // 390 source rows in tile
#define THREADS 576            // = JT*DD*8 write lanes

__global__ void __launch_bounds__(THREADS, 3)
localize_kernel(const float4* __restrict__ x, float4* __restrict__ out)
{
    __shared__ float4 s[LROWS * ROW4];   // 3120 float4 = 49920 B

    const int bh = blockIdx.z;
    const int i  = blockIdx.y;
    const int j0 = blockIdx.x * JT;
    const int t  = threadIdx.x;

    // ---- Load phase: tile + halo, zeros outside the volume ----
    const float4 zero = make_float4(0.f, 0.f, 0.f, 0.f);
    for (int l4 = t; l4 < LROWS * ROW4; l4 += THREADS) {
        int d4  = l4 & 7;
        int row = l4 >> 3;
        int li  = row / (LJ * LK);
        int r   = row - li * (LJ * LK);
        int lj  = r / LK;
        int lk  = r - lj * LK;
        int ii  = i  + li - 1;
        int jj  = j0 + lj - 1;
        int kk  = lk - 1;
        float4 v = zero;
        if ((unsigned)ii < HH && (unsigned)jj < WW && (unsigned)kk < DD) {
            v = __ldg(&x[((size_t)bh * NN + ii * (WW * DD) + jj * DD + kk) * ROW4 + d4]);
        }
        s[l4] = v;
    }
    __syncthreads();

    // ---- Write phase: one thread per (jl, k, d4); 27 SMEM reads + 27 stores ----
    const int d4 = t & 7;
    const int nl = t >> 3;          // 0..71
    const int jl = nl / DD;         // 0..2
    const int k  = nl - jl * DD;    // 0..23

    const int n = i * (WW * DD) + (j0 + jl) * DD + k;
    float4* dst = out + ((size_t)bh * NN + n) * (FN * ROW4) + d4;
    const float4* sp = s + ((size_t)jl * LK + k) * ROW4 + d4;

    #pragma unroll
    for (int fi = 0; fi < 3; fi++) {
        #pragma unroll
        for (int fj = 0; fj < 3; fj++) {
            #pragma unroll
            for (int fk = 0; fk < 3; fk++) {
                const int soff = ((fi * LJ + fj) * LK + fk) * ROW4;
                dst[((fi * 3 + fj) * 3 + fk) * ROW4] = sp[soff];   // default policy
            }
        }
    }
}

extern "C" void kernel_launch(void* const* d_in, const int* in_sizes, int n_in,
                              void* d_out, int out_size)
{
    const float4* x = (const float4*)d_in[0];
    float4* out = (float4*)d_out;

    int BH = out_size / (NN * FN * 32);     // batch*heads (16 for reference shapes)
    dim3 grid(WW / JT, HH, BH);
    localize_kernel<<<grid, THREADS>>>(x, out);
}